// round 10
// baseline (speedup 1.0000x reference)
#include <cuda_runtime.h>

// Problem constants
#define B_  32
#define N_  325
#define K_  20
#define SIN 12
#define S_  12      // S_OUT
#define C_  10
#define H_  48      // 4*S_OUT
#define BN  (B_ * N_)          // 10400
#define WPB 4                  // warps per block in k_main (128 threads)
#define MAIN_BLOCKS (BN / WPB)             // 2600
#define EMB_BLOCKS ((2 * BN + 255) / 256)  // 82

typedef unsigned long long ull;

// Scratch (device globals: no allocation allowed)
__device__ float g_wh[BN * S_];
__device__ float g_hx[BN * H_];      // includes +a1b (pre-biased)
__device__ float g_hy[BN * H_];
__device__ float g_whp[EMB_BLOCKS];
__device__ float g_clp[BN];
__device__ float g_dsp[BN];
__device__ unsigned int g_done = 0;  // last-block counter (self-resetting)

// ---- packed f32x2 helpers (SASS FFMA2 — PTX-only path) ----
__device__ __forceinline__ void ffma2(ull& d, ull a, ull b) {
    asm("fma.rn.f32x2 %0, %1, %2, %0;" : "+l"(d) : "l"(a), "l"(b));
}
__device__ __forceinline__ ull fma2v(ull a, ull b, ull c) {
    ull r; asm("fma.rn.f32x2 %0, %1, %2, %3;" : "=l"(r) : "l"(a), "l"(b), "l"(c)); return r;
}
__device__ __forceinline__ ull mul2(ull a, ull b) {
    ull r; asm("mul.rn.f32x2 %0, %1, %2;" : "=l"(r) : "l"(a), "l"(b)); return r;
}
__device__ __forceinline__ ull add2(ull a, ull b) {
    ull r; asm("add.rn.f32x2 %0, %1, %2;" : "=l"(r) : "l"(a), "l"(b)); return r;
}
__device__ __forceinline__ ull pack2(float lo, float hi) {
    ull r; asm("mov.b64 %0, {%1, %2};" : "=l"(r) : "f"(lo), "f"(hi)); return r;
}
__device__ __forceinline__ float sum2(ull v) {
    float lo, hi; asm("mov.b64 {%0, %1}, %2;" : "=f"(lo), "=f"(hi) : "l"(v)); return lo + hi;
}
__device__ __forceinline__ float low2(ull v) {
    float lo, hi; asm("mov.b64 {%0, %1}, %2;" : "=f"(lo), "=f"(hi) : "l"(v)); return lo;
}
#define C75 0x3F4000003F400000ULL   // (0.75f, 0.75f)
#define C25 0x3E8000003E800000ULL   // (0.25f, 0.25f)
// leaky-0.5 packed: 0.75x + 0.25|x|
__device__ __forceinline__ ull lrelu2(ull x) {
    ull a = x & 0x7FFFFFFF7FFFFFFFULL;
    return fma2v(x, C75, mul2(a, C25));
}
__device__ __forceinline__ float lrelu(float x) { return fmaxf(x, 0.5f * x); }

// ---------------------------------------------------------------------------
// Kernel 1: wh = leaky(x @ w_W + w_b); hx = wh @ a1_W[:12] + a1b; hy = wh @ a1_W[12:]
// Two threads per row. Weights packed into f32x2 pairs in-block.
// ---------------------------------------------------------------------------
__global__ void __launch_bounds__(256)
k_embed(const float* __restrict__ in, const float* __restrict__ wW,
        const float* __restrict__ wb, const float* __restrict__ a1W,
        const float* __restrict__ a1b) {
    __shared__ __align__(16) ull s_wwh[S_ * 6];     // [j][ip]
    __shared__ __align__(16) ull s_wa1[96 * 6];     // [o][ip], o = half*48 + j
    __shared__ float s_wb[S_];
    __shared__ float s_a1b[H_];
    __shared__ float s_red[8];

    int t = threadIdx.x;
    for (int d = t; d < S_ * 6; d += 256) {
        int j = d / 6, ip = d % 6;
        s_wwh[d] = pack2(wW[(2 * ip) * S_ + j], wW[(2 * ip + 1) * S_ + j]);
    }
    for (int d = t; d < 96 * 6; d += 256) {
        int o = d / 6, ip = d % 6;
        int half = o / H_, j = o % H_;
        s_wa1[d] = pack2(a1W[(half * S_ + 2 * ip) * H_ + j],
                         a1W[(half * S_ + 2 * ip + 1) * H_ + j]);
    }
    if (t < S_) s_wb[t] = wb[t];
    if (t < H_) s_a1b[t] = a1b[t];
    __syncthreads();

    int gid  = blockIdx.x * 256 + t;
    int row  = gid >> 1;
    int half = gid & 1;
    float whsum = 0.0f;

    if (row < BN) {
        const ulonglong2* xv = (const ulonglong2*)(in + row * SIN);
        ulonglong2 x0 = xv[0], x1 = xv[1], x2 = xv[2];
        ull xp[6] = {x0.x, x0.y, x1.x, x1.y, x2.x, x2.y};

        float wh[S_];
        #pragma unroll
        for (int j = 0; j < S_; j++) {
            const ulonglong2* wr = (const ulonglong2*)(s_wwh + j * 6);
            ulonglong2 w0 = wr[0], w1 = wr[1], w2 = wr[2];
            ull acc = 0;
            ffma2(acc, xp[0], w0.x); ffma2(acc, xp[1], w0.y);
            ffma2(acc, xp[2], w1.x); ffma2(acc, xp[3], w1.y);
            ffma2(acc, xp[4], w2.x); ffma2(acc, xp[5], w2.y);
            wh[j] = lrelu(sum2(acc) + s_wb[j]);
        }
        if (half == 0) {
            float4* wo = (float4*)(g_wh + row * S_);
            wo[0] = make_float4(wh[0], wh[1], wh[2], wh[3]);
            wo[1] = make_float4(wh[4], wh[5], wh[6], wh[7]);
            wo[2] = make_float4(wh[8], wh[9], wh[10], wh[11]);
            #pragma unroll
            for (int j = 0; j < S_; j++) whsum += wh[j];
        }
        ull whp[6];
        #pragma unroll
        for (int q = 0; q < 6; q++) whp[q] = pack2(wh[2 * q], wh[2 * q + 1]);

        float* dst = (half == 0 ? g_hx : g_hy) + row * H_;
        #pragma unroll
        for (int j4 = 0; j4 < 12; j4++) {
            float o[4];
            #pragma unroll
            for (int jj = 0; jj < 4; jj++) {
                int jo = j4 * 4 + jj;
                const ulonglong2* wr = (const ulonglong2*)(s_wa1 + (half * H_ + jo) * 6);
                ulonglong2 w0 = wr[0], w1 = wr[1], w2 = wr[2];
                ull acc = 0;
                ffma2(acc, whp[0], w0.x); ffma2(acc, whp[1], w0.y);
                ffma2(acc, whp[2], w1.x); ffma2(acc, whp[3], w1.y);
                ffma2(acc, whp[4], w2.x); ffma2(acc, whp[5], w2.y);
                float v = sum2(acc);
                if (half == 0) v += s_a1b[jo];     // pre-bias hx
                o[jj] = v;
            }
            ((float4*)dst)[j4] = make_float4(o[0], o[1], o[2], o[3]);
        }
    }
    #pragma unroll
    for (int off = 16; off > 0; off >>= 1)
        whsum += __shfl_down_sync(0xffffffffu, whsum, off);
    if ((t & 31) == 0) s_red[t >> 5] = whsum;
    __syncthreads();
    if (t == 0) {
        float s = 0.0f;
        #pragma unroll
        for (int w = 0; w < 8; w++) s += s_red[w];
        g_whp[blockIdx.x] = s;
    }
}

// ---------------------------------------------------------------------------
// Kernel 2: ONE WARP per (b,n), lane k owns neighbor k. Direct per-lane
// gathers (lean body), 4 warps/block for 10 blocks/SM occupancy.
// Last finishing block performs the final scalar reduction.
// ---------------------------------------------------------------------------
__global__ void __launch_bounds__(128, 10)
k_main(const int* __restrict__ idxp, const float* __restrict__ a2W,
       const float* __restrict__ a2b, float* __restrict__ out, int scalar_base) {
    __shared__ __align__(16) ull s_w2[24 * C_];          // packed a2W pairs [p][c]
    __shared__ float s_a2b[12];
    __shared__ __align__(16) float s_att[WPB][K_ * 12];  // att rows + invn in slot 10
    __shared__ __align__(16) float s_wht[WPB][K_ * 12];  // raw wh_topk rows
    __shared__ bool s_last;
    __shared__ double s_dred[2][WPB];
    __shared__ float s_wred[WPB];

    int t = threadIdx.x;
    int w = t >> 5;
    int lane = t & 31;
    int bn = blockIdx.x * WPB + w;
    int b  = bn / N_;

    for (int d = t; d < 24 * C_; d += 128) {
        int p = d / C_, c = d % C_;
        s_w2[d] = pack2(a2W[(2 * p) * C_ + c], a2W[(2 * p + 1) * C_ + c]);
    }
    if (t < C_) s_a2b[t] = a2b[t];
    __syncthreads();

    bool act = lane < K_;
    float att[C_];
    float invn = 0.0f;
    float4 wq0, wq1, wq2;

    if (act) {
        int nb = idxp[bn * K_ + lane];
        int base = b * N_ + nb;
        const ulonglong2* hyp = (const ulonglong2*)(g_hy + base * H_);
        const ulonglong2* hxp = (const ulonglong2*)(g_hx + bn * H_);   // uniform
        const float4* whr = (const float4*)(g_wh + base * S_);
        wq0 = whr[0]; wq1 = whr[1]; wq2 = whr[2];

        ull acc2[C_];
        #pragma unroll
        for (int c = 0; c < C_; c++) acc2[c] = 0;

        #pragma unroll
        for (int q = 0; q < 12; q++) {
            ulonglong2 hy2 = hyp[q];
            ulonglong2 hx2 = hxp[q];
            ull h0 = lrelu2(add2(hy2.x, hx2.x));
            ull h1 = lrelu2(add2(hy2.y, hx2.y));
            const ulonglong2* wr0 = (const ulonglong2*)(s_w2 + (2 * q) * C_);
            const ulonglong2* wr1 = (const ulonglong2*)(s_w2 + (2 * q + 1) * C_);
            #pragma unroll
            for (int cp = 0; cp < 5; cp++) {
                ulonglong2 w0 = wr0[cp];           // broadcast LDS.128
                ffma2(acc2[2 * cp],     h0, w0.x);
                ffma2(acc2[2 * cp + 1], h0, w0.y);
                ulonglong2 w1 = wr1[cp];
                ffma2(acc2[2 * cp],     h1, w1.x);
                ffma2(acc2[2 * cp + 1], h1, w1.y);
            }
        }
        float m = -1e30f;
        #pragma unroll
        for (int c = 0; c < C_; c++) {
            float v = sum2(acc2[c]) + s_a2b[c];
            att[c] = lrelu(v);
            m = fmaxf(m, att[c]);
        }
        float sum = 0.0f;
        #pragma unroll
        for (int c = 0; c < C_; c++) { att[c] = __expf(att[c] - m); sum += att[c]; }
        float inv = 1.0f / sum;
        #pragma unroll
        for (int c = 0; c < C_; c++) att[c] *= inv;

        // inverse norm of raw wht (dist normalization folded into pairs phase)
        float nq = wq0.x*wq0.x + wq0.y*wq0.y + wq0.z*wq0.z + wq0.w*wq0.w
                 + wq1.x*wq1.x + wq1.y*wq1.y + wq1.z*wq1.z + wq1.w*wq1.w
                 + wq2.x*wq2.x + wq2.y*wq2.y + wq2.z*wq2.z + wq2.w*wq2.w;
        invn = __fdividef(1.0f, sqrtf(nq) + 1e-8f);

        float4* ar = (float4*)(s_att[w] + lane * 12);
        ar[0] = make_float4(att[0], att[1], att[2], att[3]);
        ar[1] = make_float4(att[4], att[5], att[6], att[7]);
        ar[2] = make_float4(att[8], att[9], invn, 0.0f);       // invn in slot 10
        float4* wr = (float4*)(s_wht[w] + lane * 12);
        wr[0] = wq0; wr[1] = wq1; wr[2] = wq2;
    }
    __syncwarp();

    // output_data[b,n,c,s] = sum_k att[k][c] * wht[k][s]  (30 lanes, quad each)
    if (lane < 30) {
        int c = lane / 3, sq = lane % 3;
        float4 acc = make_float4(0.f, 0.f, 0.f, 0.f);
        #pragma unroll
        for (int k = 0; k < K_; k++) {
            float a = s_att[w][k * 12 + c];
            float4 v = ((const float4*)(s_wht[w] + k * 12))[sq];
            acc.x += a * v.x; acc.y += a * v.y; acc.z += a * v.z; acc.w += a * v.w;
        }
        ((float4*)out)[bn * 30 + lane] = acc;
    }

    // pairs (k = lane, l = 0..19): dist (raw dot * inv_k * inv_l) + cluster loss
    float cl = 0.0f, ds = 0.0f;
    if (act) {
        ull wp[6], ap[5];
        wp[0] = pack2(wq0.x, wq0.y); wp[1] = pack2(wq0.z, wq0.w);
        wp[2] = pack2(wq1.x, wq1.y); wp[3] = pack2(wq1.z, wq1.w);
        wp[4] = pack2(wq2.x, wq2.y); wp[5] = pack2(wq2.z, wq2.w);
        #pragma unroll
        for (int q = 0; q < 5; q++) ap[q] = pack2(att[2 * q], att[2 * q + 1]);
        float inv_k = invn;

        #pragma unroll
        for (int l = 0; l < K_; l++) {
            const ulonglong2* wl = (const ulonglong2*)(s_wht[w] + l * 12);
            ulonglong2 v0 = wl[0], v1 = wl[1], v2 = wl[2];     // broadcast
            ull d2 = 0;
            ffma2(d2, wp[0], v0.x); ffma2(d2, wp[1], v0.y);
            ffma2(d2, wp[2], v1.x); ffma2(d2, wp[3], v1.y);
            ffma2(d2, wp[4], v2.x); ffma2(d2, wp[5], v2.y);
            const ulonglong2* al = (const ulonglong2*)(s_att[w] + l * 12);
            ulonglong2 a0 = al[0], a1 = al[1], a2q = al[2];    // a2q.y low = inv_l
            float inv_l = low2(a2q.y);
            float d = sum2(d2) * inv_k * inv_l;
            ds += d;
            if (l != lane) {
                ull p2 = 0;
                ffma2(p2, ap[0], a0.x); ffma2(p2, ap[1], a0.y);
                ffma2(p2, ap[2], a1.x); ffma2(p2, ap[3], a1.y);
                ffma2(p2, ap[4], a2q.x);
                float p = sum2(p2);
                p = fminf(fmaxf(p, 1e-4f), 1.0f - 1e-4f);
                float lp = __logf(p);
                cl += (d >= 0.5f) ? -lp : lp;
            }
        }
    }
    #pragma unroll
    for (int off = 16; off > 0; off >>= 1) {
        cl += __shfl_down_sync(0xffffffffu, cl, off);
        ds += __shfl_down_sync(0xffffffffu, ds, off);
    }
    if (lane == 0) { g_clp[bn] = cl; g_dsp[bn] = ds; }

    // ---- last finishing block performs the final scalar reduction ----
    __syncthreads();
    if (t == 0) {
        __threadfence();
        unsigned int v = atomicAdd(&g_done, 1u);
        s_last = (v == MAIN_BLOCKS - 1);
    }
    __syncthreads();
    if (!s_last) return;
    if (t == 0) g_done = 0;   // reset for next graph replay

    double cld = 0.0, dsd = 0.0, whd = 0.0;
    for (int i = t; i < BN; i += 128) {
        cld += (double)__ldcg(&g_clp[i]);
        dsd += (double)__ldcg(&g_dsp[i]);
    }
    for (int i = t; i < EMB_BLOCKS; i += 128) whd += (double)__ldcg(&g_whp[i]);

    #pragma unroll
    for (int off = 16; off > 0; off >>= 1) {
        cld += __shfl_down_sync(0xffffffffu, cld, off);
        dsd += __shfl_down_sync(0xffffffffu, dsd, off);
        whd += __shfl_down_sync(0xffffffffu, whd, off);
    }
    if (lane == 0) { s_dred[0][w] = cld; s_dred[1][w] = dsd; s_wred[w] = (float)whd; }
    __syncthreads();
    if (t == 0) {
        double c = 0.0, d = 0.0, wh = 0.0;
        #pragma unroll
        for (int i = 0; i < WPB; i++) {
            c += s_dred[0][i]; d += s_dred[1][i]; wh += (double)s_wred[i];
        }
        out[scalar_base + 0] = (float)(c / (double)BN);
        out[scalar_base + 1] = (float)(d / ((double)BN * K_ * K_));
        out[scalar_base + 2] = (float)(wh / ((double)BN * S_));
    }
}

// ---------------------------------------------------------------------------
// Launch. Input order: fushed_features (unused), input_data, w_W, w_b,
// a1_W, a1_b, a2_W, a2_b, adj_mx_topk_index.
// ---------------------------------------------------------------------------
extern "C" void kernel_launch(void* const* d_in, const int* in_sizes, int n_in,
                              void* d_out, int out_size) {
    const float* input_data = (const float*)d_in[1];
    const float* wW  = (const float*)d_in[2];
    const float* wb  = (const float*)d_in[3];
    const float* a1W = (const float*)d_in[4];
    const float* a1b = (const float*)d_in[5];
    const float* a2W = (const float*)d_in[6];
    const float* a2b = (const float*)d_in[7];
    const int*   idx = (const int*)d_in[8];
    float* out = (float*)d_out;

    k_embed<<<EMB_BLOCKS, 256>>>(input_data, wW, wb, a1W, a1b);
    k_main<<<MAIN_BLOCKS, 128>>>(idx, a2W, a2b, out, out_size - 3);
}

// round 14
// speedup vs baseline: 1.0643x; 1.0643x over previous
#include <cuda_runtime.h>

// Problem constants
#define B_  32
#define N_  325
#define K_  20
#define SIN 12
#define S_  12      // S_OUT
#define C_  10
#define H_  48      // 4*S_OUT
#define BN  (B_ * N_)          // 10400
#define WPB 8                  // warps per block in k_main (256 threads)
#define MAIN_BLOCKS (BN / WPB)             // 1300
#define EMB_BLOCKS ((2 * BN + 255) / 256)  // 82

typedef unsigned long long ull;

// Scratch (device globals: no allocation allowed)
__device__ float g_wh[BN * S_];
__device__ float g_hx[BN * H_];      // includes +a1b (pre-biased)
__device__ float g_hy[BN * H_];
__device__ float g_whp[EMB_BLOCKS];
__device__ float g_clp[BN];
__device__ float g_dsp[BN];
__device__ unsigned int g_done = 0;  // last-block counter (self-resetting)

// ---- packed f32x2 helpers (SASS FFMA2 — PTX-only path) ----
__device__ __forceinline__ void ffma2(ull& d, ull a, ull b) {
    asm("fma.rn.f32x2 %0, %1, %2, %0;" : "+l"(d) : "l"(a), "l"(b));
}
__device__ __forceinline__ ull fma2v(ull a, ull b, ull c) {
    ull r; asm("fma.rn.f32x2 %0, %1, %2, %3;" : "=l"(r) : "l"(a), "l"(b), "l"(c)); return r;
}
__device__ __forceinline__ ull mul2(ull a, ull b) {
    ull r; asm("mul.rn.f32x2 %0, %1, %2;" : "=l"(r) : "l"(a), "l"(b)); return r;
}
__device__ __forceinline__ ull add2(ull a, ull b) {
    ull r; asm("add.rn.f32x2 %0, %1, %2;" : "=l"(r) : "l"(a), "l"(b)); return r;
}
__device__ __forceinline__ ull pack2(float lo, float hi) {
    ull r; asm("mov.b64 %0, {%1, %2};" : "=l"(r) : "f"(lo), "f"(hi)); return r;
}
__device__ __forceinline__ float sum2(ull v) {
    float lo, hi; asm("mov.b64 {%0, %1}, %2;" : "=f"(lo), "=f"(hi) : "l"(v)); return lo + hi;
}
__device__ __forceinline__ float low2(ull v) {
    float lo, hi; asm("mov.b64 {%0, %1}, %2;" : "=f"(lo), "=f"(hi) : "l"(v)); return lo;
}
#define C75 0x3F4000003F400000ULL   // (0.75f, 0.75f)
#define C25 0x3E8000003E800000ULL   // (0.25f, 0.25f)
// leaky-0.5 packed: 0.75x + 0.25|x|
__device__ __forceinline__ ull lrelu2(ull x) {
    ull a = x & 0x7FFFFFFF7FFFFFFFULL;
    return fma2v(x, C75, mul2(a, C25));
}
__device__ __forceinline__ float lrelu(float x) { return fmaxf(x, 0.5f * x); }

// ---------------------------------------------------------------------------
// Kernel 1: wh = leaky(x @ w_W + w_b); hx = wh @ a1_W[:12] + a1b; hy = wh @ a1_W[12:]
// Two threads per row. Weights packed into f32x2 pairs in-block.
// ---------------------------------------------------------------------------
__global__ void __launch_bounds__(256)
k_embed(const float* __restrict__ in, const float* __restrict__ wW,
        const float* __restrict__ wb, const float* __restrict__ a1W,
        const float* __restrict__ a1b) {
    __shared__ __align__(16) ull s_wwh[S_ * 6];     // [j][ip]
    __shared__ __align__(16) ull s_wa1[96 * 6];     // [o][ip], o = half*48 + j
    __shared__ float s_wb[S_];
    __shared__ float s_a1b[H_];
    __shared__ float s_red[8];

    int t = threadIdx.x;
    for (int d = t; d < S_ * 6; d += 256) {
        int j = d / 6, ip = d % 6;
        s_wwh[d] = pack2(wW[(2 * ip) * S_ + j], wW[(2 * ip + 1) * S_ + j]);
    }
    for (int d = t; d < 96 * 6; d += 256) {
        int o = d / 6, ip = d % 6;
        int half = o / H_, j = o % H_;
        s_wa1[d] = pack2(a1W[(half * S_ + 2 * ip) * H_ + j],
                         a1W[(half * S_ + 2 * ip + 1) * H_ + j]);
    }
    if (t < S_) s_wb[t] = wb[t];
    if (t < H_) s_a1b[t] = a1b[t];
    __syncthreads();

    int gid  = blockIdx.x * 256 + t;
    int row  = gid >> 1;
    int half = gid & 1;
    float whsum = 0.0f;

    if (row < BN) {
        const ulonglong2* xv = (const ulonglong2*)(in + row * SIN);
        ulonglong2 x0 = xv[0], x1 = xv[1], x2 = xv[2];
        ull xp[6] = {x0.x, x0.y, x1.x, x1.y, x2.x, x2.y};

        float wh[S_];
        #pragma unroll
        for (int j = 0; j < S_; j++) {
            const ulonglong2* wr = (const ulonglong2*)(s_wwh + j * 6);
            ulonglong2 w0 = wr[0], w1 = wr[1], w2 = wr[2];
            ull acc = 0;
            ffma2(acc, xp[0], w0.x); ffma2(acc, xp[1], w0.y);
            ffma2(acc, xp[2], w1.x); ffma2(acc, xp[3], w1.y);
            ffma2(acc, xp[4], w2.x); ffma2(acc, xp[5], w2.y);
            wh[j] = lrelu(sum2(acc) + s_wb[j]);
        }
        if (half == 0) {
            float4* wo = (float4*)(g_wh + row * S_);
            wo[0] = make_float4(wh[0], wh[1], wh[2], wh[3]);
            wo[1] = make_float4(wh[4], wh[5], wh[6], wh[7]);
            wo[2] = make_float4(wh[8], wh[9], wh[10], wh[11]);
            #pragma unroll
            for (int j = 0; j < S_; j++) whsum += wh[j];
        }
        ull whp[6];
        #pragma unroll
        for (int q = 0; q < 6; q++) whp[q] = pack2(wh[2 * q], wh[2 * q + 1]);

        float* dst = (half == 0 ? g_hx : g_hy) + row * H_;
        #pragma unroll
        for (int j4 = 0; j4 < 12; j4++) {
            float o[4];
            #pragma unroll
            for (int jj = 0; jj < 4; jj++) {
                int jo = j4 * 4 + jj;
                const ulonglong2* wr = (const ulonglong2*)(s_wa1 + (half * H_ + jo) * 6);
                ulonglong2 w0 = wr[0], w1 = wr[1], w2 = wr[2];
                ull acc = 0;
                ffma2(acc, whp[0], w0.x); ffma2(acc, whp[1], w0.y);
                ffma2(acc, whp[2], w1.x); ffma2(acc, whp[3], w1.y);
                ffma2(acc, whp[4], w2.x); ffma2(acc, whp[5], w2.y);
                float v = sum2(acc);
                if (half == 0) v += s_a1b[jo];     // pre-bias hx
                o[jj] = v;
            }
            ((float4*)dst)[j4] = make_float4(o[0], o[1], o[2], o[3]);
        }
    }
    #pragma unroll
    for (int off = 16; off > 0; off >>= 1)
        whsum += __shfl_down_sync(0xffffffffu, whsum, off);
    if ((t & 31) == 0) s_red[t >> 5] = whsum;
    __syncthreads();
    if (t == 0) {
        float s = 0.0f;
        #pragma unroll
        for (int w = 0; w < 8; w++) s += s_red[w];
        g_whp[blockIdx.x] = s;
    }
}

// ---------------------------------------------------------------------------
// Kernel 2: ONE WARP per (b,n), lane k owns neighbor k. Lean direct gathers,
// 256-thr blocks, reg-capped for 5 blocks/SM (40 warps).
// Last finishing block performs the final scalar reduction.
// ---------------------------------------------------------------------------
__global__ void __launch_bounds__(256, 5)
k_main(const int* __restrict__ idxp, const float* __restrict__ a2W,
       const float* __restrict__ a2b, float* __restrict__ out, int scalar_base) {
    __shared__ __align__(16) ull s_w2[24 * C_];          // packed a2W pairs [p][c]
    __shared__ float s_a2b[12];
    __shared__ __align__(16) float s_att[WPB][K_ * 12];  // att rows + invn in slot 10
    __shared__ __align__(16) float s_wht[WPB][K_ * 12];  // raw wh_topk rows
    __shared__ bool s_last;
    __shared__ double s_dred[2][WPB];
    __shared__ float s_wred[WPB];

    int t = threadIdx.x;
    int w = t >> 5;
    int lane = t & 31;
    int bn = blockIdx.x * WPB + w;
    int b  = bn / N_;

    // single-pass predicated weight prologue (240 elements, 256 threads)
    if (t < 24 * C_) {
        int p = t / C_, c = t % C_;
        s_w2[t] = pack2(a2W[(2 * p) * C_ + c], a2W[(2 * p + 1) * C_ + c]);
    }
    if (t < C_) s_a2b[t] = a2b[t];
    __syncthreads();

    bool act = lane < K_;
    float att[C_];
    float invn = 0.0f;
    float4 wq0, wq1, wq2;

    if (act) {
        int nb = idxp[bn * K_ + lane];
        int base = b * N_ + nb;
        const ulonglong2* hyp = (const ulonglong2*)(g_hy + base * H_);
        const ulonglong2* hxp = (const ulonglong2*)(g_hx + bn * H_);   // uniform
        const float4* whr = (const float4*)(g_wh + base * S_);
        wq0 = whr[0]; wq1 = whr[1]; wq2 = whr[2];

        ull acc2[C_];
        #pragma unroll
        for (int c = 0; c < C_; c++) acc2[c] = 0;

        #pragma unroll
        for (int q = 0; q < 12; q++) {
            ulonglong2 hy2 = hyp[q];
            ulonglong2 hx2 = hxp[q];
            ull h0 = lrelu2(add2(hy2.x, hx2.x));
            ull h1 = lrelu2(add2(hy2.y, hx2.y));
            const ulonglong2* wr0 = (const ulonglong2*)(s_w2 + (2 * q) * C_);
            const ulonglong2* wr1 = (const ulonglong2*)(s_w2 + (2 * q + 1) * C_);
            #pragma unroll
            for (int cp = 0; cp < 5; cp++) {
                ulonglong2 w0 = wr0[cp];           // broadcast LDS.128
                ffma2(acc2[2 * cp],     h0, w0.x);
                ffma2(acc2[2 * cp + 1], h0, w0.y);
                ulonglong2 w1 = wr1[cp];
                ffma2(acc2[2 * cp],     h1, w1.x);
                ffma2(acc2[2 * cp + 1], h1, w1.y);
            }
        }
        float m = -1e30f;
        #pragma unroll
        for (int c = 0; c < C_; c++) {
            float v = sum2(acc2[c]) + s_a2b[c];
            att[c] = lrelu(v);
            m = fmaxf(m, att[c]);
        }
        float sum = 0.0f;
        #pragma unroll
        for (int c = 0; c < C_; c++) { att[c] = __expf(att[c] - m); sum += att[c]; }
        float inv = 1.0f / sum;
        #pragma unroll
        for (int c = 0; c < C_; c++) att[c] *= inv;

        // inverse norm of raw wht (dist normalization folded into pairs phase)
        float nq = wq0.x*wq0.x + wq0.y*wq0.y + wq0.z*wq0.z + wq0.w*wq0.w
                 + wq1.x*wq1.x + wq1.y*wq1.y + wq1.z*wq1.z + wq1.w*wq1.w
                 + wq2.x*wq2.x + wq2.y*wq2.y + wq2.z*wq2.z + wq2.w*wq2.w;
        invn = __fdividef(1.0f, sqrtf(nq) + 1e-8f);

        float4* ar = (float4*)(s_att[w] + lane * 12);
        ar[0] = make_float4(att[0], att[1], att[2], att[3]);
        ar[1] = make_float4(att[4], att[5], att[6], att[7]);
        ar[2] = make_float4(att[8], att[9], invn, 0.0f);       // invn in slot 10
        float4* wr = (float4*)(s_wht[w] + lane * 12);
        wr[0] = wq0; wr[1] = wq1; wr[2] = wq2;
    }
    __syncwarp();

    // output_data[b,n,c,s] = sum_k att[k][c] * wht[k][s]  (30 lanes, quad each)
    if (lane < 30) {
        int c = lane / 3, sq = lane % 3;
        float4 acc = make_float4(0.f, 0.f, 0.f, 0.f);
        #pragma unroll
        for (int k = 0; k < K_; k++) {
            float a = s_att[w][k * 12 + c];
            float4 v = ((const float4*)(s_wht[w] + k * 12))[sq];
            acc.x += a * v.x; acc.y += a * v.y; acc.z += a * v.z; acc.w += a * v.w;
        }
        ((float4*)out)[bn * 30 + lane] = acc;
    }

    // pairs (k = lane, l = 0..19): dist (raw dot * inv_k * inv_l) + cluster loss
    float cl = 0.0f, ds = 0.0f;
    if (act) {
        ull wp[6], ap[5];
        wp[0] = pack2(wq0.x, wq0.y); wp[1] = pack2(wq0.z, wq0.w);
        wp[2] = pack2(wq1.x, wq1.y); wp[3] = pack2(wq1.z, wq1.w);
        wp[4] = pack2(wq2.x, wq2.y); wp[5] = pack2(wq2.z, wq2.w);
        #pragma unroll
        for (int q = 0; q < 5; q++) ap[q] = pack2(att[2 * q], att[2 * q + 1]);
        float inv_k = invn;

        #pragma unroll
        for (int l = 0; l < K_; l++) {
            const ulonglong2* wl = (const ulonglong2*)(s_wht[w] + l * 12);
            ulonglong2 v0 = wl[0], v1 = wl[1], v2 = wl[2];     // broadcast
            ull d2 = 0;
            ffma2(d2, wp[0], v0.x); ffma2(d2, wp[1], v0.y);
            ffma2(d2, wp[2], v1.x); ffma2(d2, wp[3], v1.y);
            ffma2(d2, wp[4], v2.x); ffma2(d2, wp[5], v2.y);
            const ulonglong2* al = (const ulonglong2*)(s_att[w] + l * 12);
            ulonglong2 a0 = al[0], a1 = al[1], a2q = al[2];    // a2q.y low = inv_l
            float inv_l = low2(a2q.y);
            float d = sum2(d2) * inv_k * inv_l;
            ds += d;
            if (l != lane) {
                ull p2 = 0;
                ffma2(p2, ap[0], a0.x); ffma2(p2, ap[1], a0.y);
                ffma2(p2, ap[2], a1.x); ffma2(p2, ap[3], a1.y);
                ffma2(p2, ap[4], a2q.x);
                float p = sum2(p2);
                p = fminf(fmaxf(p, 1e-4f), 1.0f - 1e-4f);
                float lp = __logf(p);
                cl += (d >= 0.5f) ? -lp : lp;
            }
        }
    }
    #pragma unroll
    for (int off = 16; off > 0; off >>= 1) {
        cl += __shfl_down_sync(0xffffffffu, cl, off);
        ds += __shfl_down_sync(0xffffffffu, ds, off);
    }
    if (lane == 0) { g_clp[bn] = cl; g_dsp[bn] = ds; }

    // ---- last finishing block performs the final scalar reduction ----
    __syncthreads();
    if (t == 0) {
        __threadfence();
        unsigned int v = atomicAdd(&g_done, 1u);
        s_last = (v == MAIN_BLOCKS - 1);
    }
    __syncthreads();
    if (!s_last) return;
    if (t == 0) g_done = 0;   // reset for next graph replay

    double cld = 0.0, dsd = 0.0, whd = 0.0;
    for (int i = t; i < BN; i += 256) {
        cld += (double)__ldcg(&g_clp[i]);
        dsd += (double)__ldcg(&g_dsp[i]);
    }
    for (int i = t; i < EMB_BLOCKS; i += 256) whd += (double)__ldcg(&g_whp[i]);

    #pragma unroll
    for (int off = 16; off > 0; off >>= 1) {
        cld += __shfl_down_sync(0xffffffffu, cld, off);
        dsd += __shfl_down_sync(0xffffffffu, dsd, off);
        whd += __shfl_down_sync(0xffffffffu, whd, off);
    }
    if (lane == 0) { s_dred[0][w] = cld; s_dred[1][w] = dsd; s_wred[w] = (float)whd; }
    __syncthreads();
    if (t == 0) {
        double c = 0.0, d = 0.0, wh = 0.0;
        #pragma unroll
        for (int i = 0; i < WPB; i++) {
            c += s_dred[0][i]; d += s_dred[1][i]; wh += (double)s_wred[i];
        }
        out[scalar_base + 0] = (float)(c / (double)BN);
        out[scalar_base + 1] = (float)(d / ((double)BN * K_ * K_));
        out[scalar_base + 2] = (float)(wh / ((double)BN * S_));
    }
}

// ---------------------------------------------------------------------------
// Launch. Input order: fushed_features (unused), input_data, w_W, w_b,
// a1_W, a1_b, a2_W, a2_b, adj_mx_topk_index.
// ---------------------------------------------------------------------------
extern "C" void kernel_launch(void* const* d_in, const int* in_sizes, int n_in,
                              void* d_out, int out_size) {
    const float* input_data = (const float*)d_in[1];
    const float* wW  = (const float*)d_in[2];
    const float* wb  = (const float*)d_in[3];
    const float* a1W = (const float*)d_in[4];
    const float* a1b = (const float*)d_in[5];
    const float* a2W = (const float*)d_in[6];
    const float* a2b = (const float*)d_in[7];
    const int*   idx = (const int*)d_in[8];
    float* out = (float*)d_out;

    k_embed<<<EMB_BLOCKS, 256>>>(input_data, wW, wb, a1W, a1b);
    k_main<<<MAIN_BLOCKS, 256>>>(idx, a2W, a2b, out, out_size - 3);
}